// round 1
// baseline (speedup 1.0000x reference)
#include <cuda_runtime.h>
#include <math.h>

// ---------------- problem constants ----------------
#define IMGD   64
#define BATCH  512
#define UNITS  256
#define STEPS  10
#define GATE   (4*UNITS)          // 1024
#define PIX    (IMGD*IMGD)        // 4096
#define K_ENC  (PIX + 2*UNITS)    // 4608  = [x_hat | h_enc | h_dec]
#define K_DEC  (2*UNITS)          // 512   = [z | h_dec]

// ---------------- scratch (device globals; no alloc allowed) ----------------
__device__ __align__(16) float g_W1[K_ENC * GATE];   // stacked enc weight (18.9 MB)
__device__ __align__(16) float g_W2[K_DEC * GATE];   // stacked dec weight (2 MB)
__device__ __align__(16) float g_A [BATCH * K_ENC];  // enc input  [x_hat | h_enc | h_dec]
__device__ __align__(16) float g_Ad[BATCH * K_DEC];  // dec input  [z | h_dec]
__device__ __align__(16) float g_Z [BATCH * GATE];   // enc gates
__device__ __align__(16) float g_Zd[BATCH * GATE];   // dec gates
__device__ __align__(16) float g_ce[BATCH * UNITS];  // c_enc
__device__ __align__(16) float g_cd[BATCH * UNITS];  // c_dec
__device__ __align__(16) float g_hd[BATCH * UNITS];  // h_dec (contiguous, for canvas GEMM)

__device__ __forceinline__ float sigmoidf(float x) { return 1.f / (1.f + expf(-x)); }

// ---------------- setup kernels ----------------
__global__ void zero_kernel(float* p, int n) {
    int i = blockIdx.x * blockDim.x + threadIdx.x;
    if (i < n) p[i] = 0.f;
}

// Fold patch-extraction into a [4096,1024] pixel matrix + stack enc_rec + (h_dec weight x2).
// enc_kernel layout rows: [0,9216) patches ((pr*32+pc)*9 + dr*3+dc), [9216,9472) h_dec#1, [9472,9728) h_dec#2
__global__ void build_w1_kernel(const float* __restrict__ ek, const float* __restrict__ er) {
    int idx = blockIdx.x * blockDim.x + threadIdx.x;
    if (idx >= K_ENC * GATE) return;
    int row = idx / GATE;
    int n   = idx - row * GATE;
    float v;
    if (row < PIX) {
        int r = row >> 6, c = row & 63;
        v = 0.f;
        #pragma unroll
        for (int dr = 0; dr < 3; dr++) {
            int rr = r - dr;
            if (rr >= 0 && (rr & 1) == 0) {          // pr = rr/2, stride-2, pad_lo = 0
                int pr = rr >> 1;                     // always < 32 here
                #pragma unroll
                for (int dc = 0; dc < 3; dc++) {
                    int cc = c - dc;
                    if (cc >= 0 && (cc & 1) == 0) {
                        int pc = cc >> 1;
                        v += ek[(((pr * 32 + pc) * 9) + dr * 3 + dc) * GATE + n];
                    }
                }
            }
        }
    } else if (row < PIX + UNITS) {                   // h_enc -> enc_rec
        v = er[(row - PIX) * GATE + n];
    } else {                                          // h_dec appears twice in enc_in
        int u = row - PIX - UNITS;
        v = ek[(9216 + u) * GATE + n] + ek[(9472 + u) * GATE + n];
    }
    g_W1[idx] = v;
}

__global__ void build_w2_kernel(const float* __restrict__ dk, const float* __restrict__ dr) {
    int idx = blockIdx.x * blockDim.x + threadIdx.x;
    if (idx >= K_DEC * GATE) return;
    int row = idx / GATE;
    int n   = idx - row * GATE;
    g_W2[idx] = (row < UNITS) ? dk[row * GATE + n] : dr[(row - UNITS) * GATE + n];
}

// ---------------- per-step elementwise kernels ----------------
__global__ void xhat_kernel(const float* __restrict__ x, const float* __restrict__ canvas) {
    int i = blockIdx.x * blockDim.x + threadIdx.x;   // BATCH*PIX threads
    int b = i >> 12, p = i & (PIX - 1);
    g_A[b * K_ENC + p] = x[i] - sigmoidf(canvas[i]);
}

__global__ void lstm_kernel(const float* __restrict__ Zg, const float* __restrict__ bias,
                            float* __restrict__ c,
                            float* __restrict__ h1, int s1,
                            float* __restrict__ h2, int s2,
                            float* __restrict__ h3, int s3) {
    int idx = blockIdx.x * blockDim.x + threadIdx.x;  // BATCH*UNITS
    int b = idx / UNITS, u = idx - b * UNITS;
    const float* zr = Zg + b * GATE;
    float gi = zr[u]             + bias[u];
    float gf = zr[UNITS + u]     + bias[UNITS + u];
    float gg = zr[2 * UNITS + u] + bias[2 * UNITS + u];
    float go = zr[3 * UNITS + u] + bias[3 * UNITS + u];
    float cn = sigmoidf(gf) * c[idx] + sigmoidf(gi) * tanhf(gg);
    float hn = sigmoidf(go) * tanhf(cn);
    c[idx] = cn;
    h1[b * s1 + u] = hn;
    if (h2) h2[b * s2 + u] = hn;
    if (h3) h3[b * s3 + u] = hn;
}

// attention: logits = h_enc @ W_enc + b_enc (10), softmax, z = attn @ W_enc^T
__global__ void attn_kernel(const float* __restrict__ Wenc, const float* __restrict__ benc) {
    int b = blockIdx.x;
    int u = threadIdx.x;                      // 256
    __shared__ float lg[10];
    __shared__ float attn[10];
    if (u < 10) lg[u] = benc[u];
    __syncthreads();
    float hv = g_A[b * K_ENC + PIX + u];      // h_enc slot
    float p[10];
    #pragma unroll
    for (int j = 0; j < 10; j++) p[j] = hv * Wenc[u * 10 + j];
    #pragma unroll
    for (int j = 0; j < 10; j++)
        #pragma unroll
        for (int off = 16; off > 0; off >>= 1)
            p[j] += __shfl_down_sync(0xffffffffu, p[j], off);
    if ((u & 31) == 0)
        for (int j = 0; j < 10; j++) atomicAdd(&lg[j], p[j]);
    __syncthreads();
    if (u == 0) {
        float m = lg[0];
        for (int j = 1; j < 10; j++) m = fmaxf(m, lg[j]);
        float s = 0.f, e[10];
        for (int j = 0; j < 10; j++) { e[j] = expf(lg[j] - m); s += e[j]; }
        float inv = 1.f / s;
        for (int j = 0; j < 10; j++) attn[j] = e[j] * inv;
    }
    __syncthreads();
    float acc = 0.f;
    #pragma unroll
    for (int j = 0; j < 10; j++) acc += attn[j] * Wenc[u * 10 + j];
    g_Ad[b * K_DEC + u] = acc;                // z slot of dec input
}

// ---------------- tiled fp32 GEMM: C[M,N] (+)= A[M,K] @ B[K,N] (+ bias) ----------------
// 64x64 tile, BK=16, 256 threads, 4x4 per thread. All dims multiples of 16/64.
template <bool ACC, bool BIAS>
__global__ __launch_bounds__(256) void gemm_kernel(
    const float* __restrict__ A, int lda,
    const float* __restrict__ Bm, int ldb,
    float* __restrict__ C, int ldc,
    int K, const float* __restrict__ bias)
{
    __shared__ float As[16][68];
    __shared__ float Bs[16][68];
    const int tid = threadIdx.x;
    const int m0 = blockIdx.y * 64;
    const int n0 = blockIdx.x * 64;
    const int tx = tid & 15, ty = tid >> 4;
    const int a_row = tid >> 2;             // 0..63
    const int a_q   = (tid & 3) * 4;        // k offset 0/4/8/12
    const int b_row = tid >> 4;             // 0..15
    const int b_q   = (tid & 15) * 4;       // n offset

    float acc[4][4] = {};
    for (int k0 = 0; k0 < K; k0 += 16) {
        float4 av = *reinterpret_cast<const float4*>(&A[(m0 + a_row) * lda + k0 + a_q]);
        float4 bv = *reinterpret_cast<const float4*>(&Bm[(k0 + b_row) * ldb + n0 + b_q]);
        __syncthreads();
        As[a_q + 0][a_row] = av.x;
        As[a_q + 1][a_row] = av.y;
        As[a_q + 2][a_row] = av.z;
        As[a_q + 3][a_row] = av.w;
        *reinterpret_cast<float4*>(&Bs[b_row][b_q]) = bv;
        __syncthreads();
        #pragma unroll
        for (int kk = 0; kk < 16; kk++) {
            float4 a4 = *reinterpret_cast<const float4*>(&As[kk][ty * 4]);
            float4 b4 = *reinterpret_cast<const float4*>(&Bs[kk][tx * 4]);
            float ar[4] = {a4.x, a4.y, a4.z, a4.w};
            float br[4] = {b4.x, b4.y, b4.z, b4.w};
            #pragma unroll
            for (int i = 0; i < 4; i++)
                #pragma unroll
                for (int j = 0; j < 4; j++)
                    acc[i][j] += ar[i] * br[j];
        }
    }
    #pragma unroll
    for (int i = 0; i < 4; i++) {
        int m = m0 + ty * 4 + i;
        #pragma unroll
        for (int j = 0; j < 4; j++) {
            int n = n0 + tx * 4 + j;
            float v = acc[i][j];
            if (BIAS) v += bias[n];
            if (ACC)  v += C[m * ldc + n];
            C[m * ldc + n] = v;
        }
    }
}

// ---------------- launcher ----------------
extern "C" void kernel_launch(void* const* d_in, const int* in_sizes, int n_in,
                              void* d_out, int out_size) {
    const float* x          = (const float*)d_in[0];
    const float* enc_kernel = (const float*)d_in[1];
    const float* enc_rec    = (const float*)d_in[2];
    const float* enc_bias   = (const float*)d_in[3];
    const float* dec_kernel = (const float*)d_in[4];
    const float* dec_rec    = (const float*)d_in[5];
    const float* dec_bias   = (const float*)d_in[6];
    const float* W_enc      = (const float*)d_in[7];
    const float* b_enc      = (const float*)d_in[8];
    const float* W_dec      = (const float*)d_in[9];
    const float* b_dec      = (const float*)d_in[10];
    float* canvas = (float*)d_out;

    float *W1, *W2, *A, *Ad, *Z, *Zd, *ce, *cd, *hd;
    cudaGetSymbolAddress((void**)&W1, g_W1);
    cudaGetSymbolAddress((void**)&W2, g_W2);
    cudaGetSymbolAddress((void**)&A,  g_A);
    cudaGetSymbolAddress((void**)&Ad, g_Ad);
    cudaGetSymbolAddress((void**)&Z,  g_Z);
    cudaGetSymbolAddress((void**)&Zd, g_Zd);
    cudaGetSymbolAddress((void**)&ce, g_ce);
    cudaGetSymbolAddress((void**)&cd, g_cd);
    cudaGetSymbolAddress((void**)&hd, g_hd);

    // ---- one-time (per launch) setup ----
    build_w1_kernel<<<(K_ENC * GATE + 255) / 256, 256>>>(enc_kernel, enc_rec);
    build_w2_kernel<<<(K_DEC * GATE + 255) / 256, 256>>>(dec_kernel, dec_rec);
    zero_kernel<<<(BATCH * PIX + 255) / 256, 256>>>(canvas, BATCH * PIX);
    zero_kernel<<<(BATCH * K_ENC + 255) / 256, 256>>>(A,  BATCH * K_ENC);
    zero_kernel<<<(BATCH * K_DEC + 255) / 256, 256>>>(Ad, BATCH * K_DEC);
    zero_kernel<<<(BATCH * UNITS + 255) / 256, 256>>>(ce, BATCH * UNITS);
    zero_kernel<<<(BATCH * UNITS + 255) / 256, 256>>>(cd, BATCH * UNITS);
    zero_kernel<<<(BATCH * UNITS + 255) / 256, 256>>>(hd, BATCH * UNITS);

    // ---- 10 sequential DRAW steps ----
    for (int t = 0; t < STEPS; t++) {
        // x_hat = x - sigmoid(canvas) -> g_A[:, 0:4096]
        xhat_kernel<<<(BATCH * PIX) / 256, 256>>>(x, canvas);

        // enc gates: Z = [x_hat|h_enc|h_dec] @ W1
        gemm_kernel<false, false><<<dim3(GATE / 64, BATCH / 64), 256>>>(
            A, K_ENC, W1, GATE, Z, GATE, K_ENC, nullptr);

        // enc LSTM -> h_enc into g_A slot, c_enc
        lstm_kernel<<<(BATCH * UNITS) / 256, 256>>>(
            Z, enc_bias, ce, A + PIX, K_ENC, nullptr, 0, nullptr, 0);

        // attention -> z into g_Ad[:, 0:256]
        attn_kernel<<<BATCH, 256>>>(W_enc, b_enc);

        // dec gates: Zd = [z|h_dec] @ W2
        gemm_kernel<false, false><<<dim3(GATE / 64, BATCH / 64), 256>>>(
            Ad, K_DEC, W2, GATE, Zd, GATE, K_DEC, nullptr);

        // dec LSTM -> h_dec into g_A slot, g_Ad slot, g_hd
        lstm_kernel<<<(BATCH * UNITS) / 256, 256>>>(
            Zd, dec_bias, cd, A + PIX + UNITS, K_ENC, Ad + UNITS, K_DEC, hd, UNITS);

        // canvas += h_dec @ W_dec + b_dec
        gemm_kernel<true, true><<<dim3(PIX / 64, BATCH / 64), 256>>>(
            hd, UNITS, W_dec, PIX, canvas, PIX, UNITS, b_dec);
    }
}

// round 2
// speedup vs baseline: 1.3677x; 1.3677x over previous
#include <cuda_runtime.h>
#include <cuda_bf16.h>
#include <math.h>
#include <stdint.h>

// ---------------- problem constants ----------------
#define IMGD   64
#define BATCH  512
#define UNITS  256
#define STEPS  10
#define GATE   (4*UNITS)          // 1024
#define PIX    (IMGD*IMGD)        // 4096
#define K_ENC  (PIX + 2*UNITS)    // 4608  = [x_hat | h_enc | h_dec]
#define K_DEC  (2*UNITS)          // 512   = [z | h_dec]
#define K_CAN  UNITS              // 256
#define KP_ENC (3*K_ENC)          // 13824
#define KP_DEC (3*K_DEC)          // 1536
#define KP_CAN (3*K_CAN)          // 768

// ---------------- scratch (device globals; no alloc allowed) ----------------
__device__ __align__(16) __nv_bfloat16 g_Be[KP_ENC * GATE];  // packed enc weight (28.3 MB)
__device__ __align__(16) __nv_bfloat16 g_Bd[KP_DEC * GATE];  // packed dec weight
__device__ __align__(16) __nv_bfloat16 g_Bc[KP_CAN * PIX];   // packed canvas weight
__device__ __align__(16) __nv_bfloat16 g_Aeb[BATCH * KP_ENC]; // enc act [hi|hi|lo]
__device__ __align__(16) __nv_bfloat16 g_Adb[BATCH * KP_DEC]; // dec act
__device__ __align__(16) __nv_bfloat16 g_Acb[BATCH * KP_CAN]; // canvas act
__device__ __align__(16) float g_Z [BATCH * GATE];   // enc gates
__device__ __align__(16) float g_Zd[BATCH * GATE];   // dec gates
__device__ __align__(16) float g_ce[BATCH * UNITS];  // c_enc
__device__ __align__(16) float g_cd[BATCH * UNITS];  // c_dec
__device__ __align__(16) float g_he[BATCH * UNITS];  // h_enc (fp32, for attn)

__device__ __forceinline__ float sigmoidf(float x) { return 1.f / (1.f + expf(-x)); }

__device__ __forceinline__ void split_bf16(float v, __nv_bfloat16& hi, __nv_bfloat16& lo) {
    hi = __float2bfloat16(v);
    lo = __float2bfloat16(v - __bfloat162float(hi));
}

// ---------------- setup kernels ----------------
__global__ void zero4_kernel(float4* p, int n4) {
    int i = blockIdx.x * blockDim.x + threadIdx.x;
    if (i < n4) p[i] = make_float4(0.f, 0.f, 0.f, 0.f);
}

// Fold patch-extraction into pixel rows; stack enc_rec and the doubled h_dec block.
// Then split into bf16 hi/lo packed rows: [Whi ; Wlo ; Whi]
__global__ void build_w1_kernel(const float* __restrict__ ek, const float* __restrict__ er) {
    int idx = blockIdx.x * blockDim.x + threadIdx.x;
    if (idx >= K_ENC * GATE) return;
    int row = idx / GATE;
    int n   = idx - row * GATE;
    float v;
    if (row < PIX) {
        int r = row >> 6, c = row & 63;
        v = 0.f;
        #pragma unroll
        for (int dr = 0; dr < 3; dr++) {
            int rr = r - dr;
            if (rr >= 0 && (rr & 1) == 0) {
                int pr = rr >> 1;
                #pragma unroll
                for (int dc = 0; dc < 3; dc++) {
                    int cc = c - dc;
                    if (cc >= 0 && (cc & 1) == 0) {
                        int pc = cc >> 1;
                        v += ek[(((pr * 32 + pc) * 9) + dr * 3 + dc) * GATE + n];
                    }
                }
            }
        }
    } else if (row < PIX + UNITS) {
        v = er[(row - PIX) * GATE + n];
    } else {
        int u = row - PIX - UNITS;
        v = ek[(9216 + u) * GATE + n] + ek[(9472 + u) * GATE + n];
    }
    __nv_bfloat16 hi, lo; split_bf16(v, hi, lo);
    g_Be[(size_t)row * GATE + n]                 = hi;
    g_Be[(size_t)(K_ENC + row) * GATE + n]       = lo;
    g_Be[(size_t)(2 * K_ENC + row) * GATE + n]   = hi;
}

__global__ void build_w2_kernel(const float* __restrict__ dk, const float* __restrict__ dr) {
    int idx = blockIdx.x * blockDim.x + threadIdx.x;
    if (idx >= K_DEC * GATE) return;
    int row = idx / GATE;
    int n   = idx - row * GATE;
    float v = (row < UNITS) ? dk[row * GATE + n] : dr[(row - UNITS) * GATE + n];
    __nv_bfloat16 hi, lo; split_bf16(v, hi, lo);
    g_Bd[row * GATE + n]                 = hi;
    g_Bd[(K_DEC + row) * GATE + n]       = lo;
    g_Bd[(2 * K_DEC + row) * GATE + n]   = hi;
}

__global__ void build_wc_kernel(const float* __restrict__ wd) {
    int idx = blockIdx.x * blockDim.x + threadIdx.x;
    if (idx >= K_CAN * PIX) return;
    int row = idx / PIX;
    int n   = idx - row * PIX;
    float v = wd[idx];
    __nv_bfloat16 hi, lo; split_bf16(v, hi, lo);
    g_Bc[row * PIX + n]                 = hi;
    g_Bc[(K_CAN + row) * PIX + n]       = lo;
    g_Bc[(2 * K_CAN + row) * PIX + n]   = hi;
}

// ---------------- per-step elementwise kernels ----------------
__global__ void xhat_kernel(const float* __restrict__ x, const float* __restrict__ canvas) {
    int i = blockIdx.x * blockDim.x + threadIdx.x;   // BATCH*PIX threads
    int b = i >> 12, p = i & (PIX - 1);
    float v = x[i] - sigmoidf(canvas[i]);
    __nv_bfloat16 hi, lo; split_bf16(v, hi, lo);
    size_t base = (size_t)b * KP_ENC + p;
    g_Aeb[base]             = hi;
    g_Aeb[base + K_ENC]     = hi;
    g_Aeb[base + 2 * K_ENC] = lo;
}

__global__ void lstm_enc_kernel(const float* __restrict__ Zg, const float* __restrict__ bias) {
    int idx = blockIdx.x * blockDim.x + threadIdx.x;  // BATCH*UNITS
    int b = idx / UNITS, u = idx - b * UNITS;
    const float* zr = Zg + b * GATE;
    float gi = zr[u]             + bias[u];
    float gf = zr[UNITS + u]     + bias[UNITS + u];
    float gg = zr[2 * UNITS + u] + bias[2 * UNITS + u];
    float go = zr[3 * UNITS + u] + bias[3 * UNITS + u];
    float cn = sigmoidf(gf) * g_ce[idx] + sigmoidf(gi) * tanhf(gg);
    float hn = sigmoidf(go) * tanhf(cn);
    g_ce[idx] = cn;
    g_he[idx] = hn;
    __nv_bfloat16 hi, lo; split_bf16(hn, hi, lo);
    size_t base = (size_t)b * KP_ENC + PIX + u;
    g_Aeb[base]             = hi;
    g_Aeb[base + K_ENC]     = hi;
    g_Aeb[base + 2 * K_ENC] = lo;
}

__global__ void lstm_dec_kernel(const float* __restrict__ Zg, const float* __restrict__ bias) {
    int idx = blockIdx.x * blockDim.x + threadIdx.x;  // BATCH*UNITS
    int b = idx / UNITS, u = idx - b * UNITS;
    const float* zr = Zg + b * GATE;
    float gi = zr[u]             + bias[u];
    float gf = zr[UNITS + u]     + bias[UNITS + u];
    float gg = zr[2 * UNITS + u] + bias[2 * UNITS + u];
    float go = zr[3 * UNITS + u] + bias[3 * UNITS + u];
    float cn = sigmoidf(gf) * g_cd[idx] + sigmoidf(gi) * tanhf(gg);
    float hn = sigmoidf(go) * tanhf(cn);
    g_cd[idx] = cn;
    __nv_bfloat16 hi, lo; split_bf16(hn, hi, lo);
    size_t be = (size_t)b * KP_ENC + PIX + UNITS + u;
    g_Aeb[be]             = hi;
    g_Aeb[be + K_ENC]     = hi;
    g_Aeb[be + 2 * K_ENC] = lo;
    size_t bd = (size_t)b * KP_DEC + UNITS + u;
    g_Adb[bd]             = hi;
    g_Adb[bd + K_DEC]     = hi;
    g_Adb[bd + 2 * K_DEC] = lo;
    size_t bc = (size_t)b * KP_CAN + u;
    g_Acb[bc]             = hi;
    g_Acb[bc + K_CAN]     = hi;
    g_Acb[bc + 2 * K_CAN] = lo;
}

// attention: logits = h_enc @ W_enc + b_enc (10), softmax, z = attn @ W_enc^T
__global__ void attn_kernel(const float* __restrict__ Wenc, const float* __restrict__ benc) {
    int b = blockIdx.x;
    int u = threadIdx.x;                      // 256
    __shared__ float lg[10];
    __shared__ float attn[10];
    if (u < 10) lg[u] = benc[u];
    __syncthreads();
    float hv = g_he[b * UNITS + u];
    float p[10];
    #pragma unroll
    for (int j = 0; j < 10; j++) p[j] = hv * Wenc[u * 10 + j];
    #pragma unroll
    for (int j = 0; j < 10; j++)
        #pragma unroll
        for (int off = 16; off > 0; off >>= 1)
            p[j] += __shfl_down_sync(0xffffffffu, p[j], off);
    if ((u & 31) == 0)
        for (int j = 0; j < 10; j++) atomicAdd(&lg[j], p[j]);
    __syncthreads();
    if (u == 0) {
        float m = lg[0];
        for (int j = 1; j < 10; j++) m = fmaxf(m, lg[j]);
        float s = 0.f, e[10];
        for (int j = 0; j < 10; j++) { e[j] = expf(lg[j] - m); s += e[j]; }
        float inv = 1.f / s;
        for (int j = 0; j < 10; j++) attn[j] = e[j] * inv;
    }
    __syncthreads();
    float acc = 0.f;
    #pragma unroll
    for (int j = 0; j < 10; j++) acc += attn[j] * Wenc[u * 10 + j];
    __nv_bfloat16 hi, lo; split_bf16(acc, hi, lo);
    size_t bd = (size_t)b * KP_DEC + u;
    g_Adb[bd]             = hi;
    g_Adb[bd + K_DEC]     = hi;
    g_Adb[bd + 2 * K_DEC] = lo;
}

// ---------------- bf16 tensor-core GEMM: C[M,N] (+)= A[M,K'] @ B[K',N] (+bias) ----------------
// CTA tile 64x64, BK=32, 4 warps (2x2, warp tile 32x32), mma.m16n8k16, cp.async double buffer.
#define CP_ASYNC16(dst, src) \
    asm volatile("cp.async.cg.shared.global [%0], [%1], 16;\n" :: "r"(dst), "l"(src))

__device__ __forceinline__ void ldmatrix_x4(uint32_t* r, const void* p) {
    uint32_t a = (uint32_t)__cvta_generic_to_shared(p);
    asm volatile("ldmatrix.sync.aligned.m8n8.x4.shared.b16 {%0,%1,%2,%3}, [%4];\n"
                 : "=r"(r[0]), "=r"(r[1]), "=r"(r[2]), "=r"(r[3]) : "r"(a));
}
__device__ __forceinline__ void ldmatrix_x4_trans(uint32_t* r, const void* p) {
    uint32_t a = (uint32_t)__cvta_generic_to_shared(p);
    asm volatile("ldmatrix.sync.aligned.m8n8.x4.trans.shared.b16 {%0,%1,%2,%3}, [%4];\n"
                 : "=r"(r[0]), "=r"(r[1]), "=r"(r[2]), "=r"(r[3]) : "r"(a));
}
__device__ __forceinline__ void mma_bf16(float* d, const uint32_t* a, uint32_t b0, uint32_t b1) {
    asm volatile("mma.sync.aligned.m16n8k16.row.col.f32.bf16.bf16.f32 "
                 "{%0,%1,%2,%3}, {%4,%5,%6,%7}, {%8,%9}, {%0,%1,%2,%3};\n"
                 : "+f"(d[0]), "+f"(d[1]), "+f"(d[2]), "+f"(d[3])
                 : "r"(a[0]), "r"(a[1]), "r"(a[2]), "r"(a[3]), "r"(b0), "r"(b1));
}

template <bool ACC, bool BIAS>
__global__ void __launch_bounds__(128) gemm_bf16_kernel(
    const __nv_bfloat16* __restrict__ A, int lda,
    const __nv_bfloat16* __restrict__ B, int ldb,
    float* __restrict__ C, int ldc,
    int K, const float* __restrict__ bias)
{
    __shared__ __align__(16) __nv_bfloat16 As[2][64][40];   // padded, conflict-free
    __shared__ __align__(16) __nv_bfloat16 Bs[2][32][72];

    const int t = threadIdx.x;
    const int m0 = blockIdx.y * 64;
    const int n0 = blockIdx.x * 64;
    const int warp = t >> 5, lane = t & 31;
    const int wm = (warp >> 1) * 32, wn = (warp & 1) * 32;

    float acc[2][4][4] = {};

    auto load_stage = [&](int s, int buf) {
        int k0 = s * 32;
        #pragma unroll
        for (int i = 0; i < 2; i++) {
            int chunk = t + 128 * i;
            int row = chunk >> 2, col = (chunk & 3) * 8;
            const __nv_bfloat16* src = A + (size_t)(m0 + row) * lda + k0 + col;
            uint32_t dst = (uint32_t)__cvta_generic_to_shared(&As[buf][row][col]);
            CP_ASYNC16(dst, src);
        }
        #pragma unroll
        for (int i = 0; i < 2; i++) {
            int chunk = t + 128 * i;
            int row = chunk >> 3, col = (chunk & 7) * 8;
            const __nv_bfloat16* src = B + (size_t)(k0 + row) * ldb + n0 + col;
            uint32_t dst = (uint32_t)__cvta_generic_to_shared(&Bs[buf][row][col]);
            CP_ASYNC16(dst, src);
        }
        asm volatile("cp.async.commit_group;\n");
    };

    const int S = K / 32;
    load_stage(0, 0);
    for (int s = 0; s < S; s++) {
        int buf = s & 1;
        if (s + 1 < S) {
            load_stage(s + 1, buf ^ 1);
            asm volatile("cp.async.wait_group 1;\n");
        } else {
            asm volatile("cp.async.wait_group 0;\n");
        }
        __syncthreads();
        #pragma unroll
        for (int kk = 0; kk < 32; kk += 16) {
            uint32_t af[2][4], bf[2][4];
            #pragma unroll
            for (int mt = 0; mt < 2; mt++)
                ldmatrix_x4(af[mt], &As[buf][wm + mt * 16 + (lane & 15)][kk + (lane >> 4) * 8]);
            #pragma unroll
            for (int g = 0; g < 2; g++)
                ldmatrix_x4_trans(bf[g], &Bs[buf][kk + (lane & 15)][wn + g * 16 + (lane >> 4) * 8]);
            #pragma unroll
            for (int mt = 0; mt < 2; mt++)
                #pragma unroll
                for (int nt = 0; nt < 4; nt++)
                    mma_bf16(acc[mt][nt], af[mt], bf[nt >> 1][(nt & 1) * 2], bf[nt >> 1][(nt & 1) * 2 + 1]);
        }
        __syncthreads();
    }

    // epilogue
    #pragma unroll
    for (int mt = 0; mt < 2; mt++) {
        #pragma unroll
        for (int nt = 0; nt < 4; nt++) {
            int r  = m0 + wm + mt * 16 + (lane >> 2);
            int cc = n0 + wn + nt * 8 + (lane & 3) * 2;
            float v0 = acc[mt][nt][0], v1 = acc[mt][nt][1];
            float v2 = acc[mt][nt][2], v3 = acc[mt][nt][3];
            if (BIAS) { float b0 = bias[cc], b1 = bias[cc + 1]; v0 += b0; v1 += b1; v2 += b0; v3 += b1; }
            float2* p0 = reinterpret_cast<float2*>(&C[(size_t)r * ldc + cc]);
            float2* p1 = reinterpret_cast<float2*>(&C[(size_t)(r + 8) * ldc + cc]);
            if (ACC) {
                float2 c0 = *p0, c1 = *p1;
                v0 += c0.x; v1 += c0.y; v2 += c1.x; v3 += c1.y;
            }
            *p0 = make_float2(v0, v1);
            *p1 = make_float2(v2, v3);
        }
    }
}

// ---------------- launcher ----------------
extern "C" void kernel_launch(void* const* d_in, const int* in_sizes, int n_in,
                              void* d_out, int out_size) {
    const float* x          = (const float*)d_in[0];
    const float* enc_kernel = (const float*)d_in[1];
    const float* enc_rec    = (const float*)d_in[2];
    const float* enc_bias   = (const float*)d_in[3];
    const float* dec_kernel = (const float*)d_in[4];
    const float* dec_rec    = (const float*)d_in[5];
    const float* dec_bias   = (const float*)d_in[6];
    const float* W_enc      = (const float*)d_in[7];
    const float* b_enc      = (const float*)d_in[8];
    const float* W_dec      = (const float*)d_in[9];
    const float* b_dec      = (const float*)d_in[10];
    float* canvas = (float*)d_out;

    __nv_bfloat16 *Ae, *Ad, *Ac, *Be, *Bd, *Bc;
    float *Z, *Zd, *ce, *cd;
    cudaGetSymbolAddress((void**)&Ae, g_Aeb);
    cudaGetSymbolAddress((void**)&Ad, g_Adb);
    cudaGetSymbolAddress((void**)&Ac, g_Acb);
    cudaGetSymbolAddress((void**)&Be, g_Be);
    cudaGetSymbolAddress((void**)&Bd, g_Bd);
    cudaGetSymbolAddress((void**)&Bc, g_Bc);
    cudaGetSymbolAddress((void**)&Z,  g_Z);
    cudaGetSymbolAddress((void**)&Zd, g_Zd);
    cudaGetSymbolAddress((void**)&ce, g_ce);
    cudaGetSymbolAddress((void**)&cd, g_cd);

    // ---- setup: pack weights (bf16 hi/lo), zero states ----
    build_w1_kernel<<<(K_ENC * GATE + 255) / 256, 256>>>(enc_kernel, enc_rec);
    build_w2_kernel<<<(K_DEC * GATE + 255) / 256, 256>>>(dec_kernel, dec_rec);
    build_wc_kernel<<<(K_CAN * PIX + 255) / 256, 256>>>(W_dec);
    zero4_kernel<<<(BATCH * PIX * 4 / 16 + 255) / 256, 256>>>((float4*)canvas, BATCH * PIX * 4 / 16);
    zero4_kernel<<<(BATCH * KP_ENC * 2 / 16 + 255) / 256, 256>>>((float4*)Ae, BATCH * KP_ENC * 2 / 16);
    zero4_kernel<<<(BATCH * KP_DEC * 2 / 16 + 255) / 256, 256>>>((float4*)Ad, BATCH * KP_DEC * 2 / 16);
    zero4_kernel<<<(BATCH * KP_CAN * 2 / 16 + 255) / 256, 256>>>((float4*)Ac, BATCH * KP_CAN * 2 / 16);
    zero4_kernel<<<(BATCH * UNITS * 4 / 16 + 255) / 256, 256>>>((float4*)ce, BATCH * UNITS * 4 / 16);
    zero4_kernel<<<(BATCH * UNITS * 4 / 16 + 255) / 256, 256>>>((float4*)cd, BATCH * UNITS * 4 / 16);

    // ---- 10 sequential DRAW steps ----
    for (int t = 0; t < STEPS; t++) {
        xhat_kernel<<<(BATCH * PIX) / 256, 256>>>(x, canvas);

        gemm_bf16_kernel<false, false><<<dim3(GATE / 64, BATCH / 64), 128>>>(
            Ae, KP_ENC, Be, GATE, Z, GATE, KP_ENC, nullptr);

        lstm_enc_kernel<<<(BATCH * UNITS) / 256, 256>>>(Z, enc_bias);

        attn_kernel<<<BATCH, 256>>>(W_enc, b_enc);

        gemm_bf16_kernel<false, false><<<dim3(GATE / 64, BATCH / 64), 128>>>(
            Ad, KP_DEC, Bd, GATE, Zd, GATE, KP_DEC, nullptr);

        lstm_dec_kernel<<<(BATCH * UNITS) / 256, 256>>>(Zd, dec_bias);

        gemm_bf16_kernel<true, true><<<dim3(PIX / 64, BATCH / 64), 128>>>(
            Ac, KP_CAN, Bc, PIX, canvas, PIX, KP_CAN, b_dec);
    }
}

// round 4
// speedup vs baseline: 2.6934x; 1.9693x over previous
#include <cuda_runtime.h>
#include <cuda_bf16.h>
#include <math.h>
#include <stdint.h>

// ---------------- problem constants ----------------
#define IMGD   64
#define BATCH  512
#define UNITS  256
#define STEPS  10
#define GATE   (4*UNITS)          // 1024
#define PIX    (IMGD*IMGD)        // 4096
#define K_ENC  (PIX + 2*UNITS)    // 4608
#define K_DEC  (2*UNITS)          // 512
#define K_CAN  UNITS              // 256
#define KP_ENC (3*K_ENC)          // 13824
#define KP_DEC (3*K_DEC)          // 1536
#define KP_CAN (3*K_CAN)          // 768

#define ENC_SPLITS 9              // 13824/9 = 1536 per split (48 k32-iters)
#define DEC_SPLITS 4              // 1536/4  = 384  per split (12 k32-iters)

// ---------------- scratch (device globals; no alloc allowed) ----------------
__device__ __align__(16) __nv_bfloat16 g_Be[(size_t)KP_ENC * GATE];  // enc weight [K',N] row-major
__device__ __align__(16) __nv_bfloat16 g_Bd[(size_t)KP_DEC * GATE];  // dec weight
__device__ __align__(16) __nv_bfloat16 g_Bc[(size_t)KP_CAN * PIX];   // canvas weight
__device__ __align__(16) __nv_bfloat16 g_Aeb[(size_t)BATCH * KP_ENC]; // enc act [hi|hi|lo]
__device__ __align__(16) __nv_bfloat16 g_Adb[(size_t)BATCH * KP_DEC]; // dec act
__device__ __align__(16) __nv_bfloat16 g_Acb[(size_t)BATCH * KP_CAN]; // canvas act
__device__ __align__(16) float g_part[(size_t)ENC_SPLITS * BATCH * GATE]; // split-K partials
__device__ __align__(16) float g_ce[BATCH * UNITS];
__device__ __align__(16) float g_cd[BATCH * UNITS];

__device__ __forceinline__ float sigmoidf(float x) { return 1.f / (1.f + expf(-x)); }
__device__ __forceinline__ void split_bf16(float v, __nv_bfloat16& hi, __nv_bfloat16& lo) {
    hi = __float2bfloat16(v);
    lo = __float2bfloat16(v - __bfloat162float(hi));
}

// ---------------- PTX helpers (Ampere-era only: all compile on sm_103 base) ----
__device__ __forceinline__ uint32_t smem_u32(const void* p) {
    uint32_t a;
    asm("{ .reg .u64 t; cvta.to.shared.u64 t, %1; cvt.u32.u64 %0, t; }" : "=r"(a) : "l"(p));
    return a;
}
#define CP_ASYNC16(dst, src) \
    asm volatile("cp.async.cg.shared.global [%0], [%1], 16;\n" :: "r"(dst), "l"(src))
#define CP_COMMIT() asm volatile("cp.async.commit_group;\n")

__device__ __forceinline__ void ldmatrix_x4(uint32_t* r, const void* p) {
    uint32_t a = smem_u32(p);
    asm volatile("ldmatrix.sync.aligned.m8n8.x4.shared.b16 {%0,%1,%2,%3}, [%4];\n"
                 : "=r"(r[0]), "=r"(r[1]), "=r"(r[2]), "=r"(r[3]) : "r"(a));
}
__device__ __forceinline__ void ldmatrix_x4_trans(uint32_t* r, const void* p) {
    uint32_t a = smem_u32(p);
    asm volatile("ldmatrix.sync.aligned.m8n8.x4.trans.shared.b16 {%0,%1,%2,%3}, [%4];\n"
                 : "=r"(r[0]), "=r"(r[1]), "=r"(r[2]), "=r"(r[3]) : "r"(a));
}
__device__ __forceinline__ void mma_bf16(float* d, const uint32_t* a, uint32_t b0, uint32_t b1) {
    asm volatile("mma.sync.aligned.m16n8k16.row.col.f32.bf16.bf16.f32 "
                 "{%0,%1,%2,%3}, {%4,%5,%6,%7}, {%8,%9}, {%0,%1,%2,%3};\n"
                 : "+f"(d[0]), "+f"(d[1]), "+f"(d[2]), "+f"(d[3])
                 : "r"(a[0]), "r"(a[1]), "r"(a[2]), "r"(a[3]), "r"(b0), "r"(b1));
}

// ---------------- HMMA GEMM: 128x128 tile, BK=32, 256 thr, 4 stages, 2 CTA/SM -----
// A [M, lda] bf16 row-major; B [K', ldb] bf16 row-major.
// MODE 0: out slab z (overwrite):  out[z*512*ldc + m*ldc + n] = D
// MODE 1: canvas update + fused xhat: canvas += D + bias; aeb <- split(x - sigmoid(canvas))
#define STG_BYTES 18944          // A: 128*80 = 10240 B,  B: 32*272 = 8704 B
#define GEMM_SMEM (4 * STG_BYTES)

template<int MODE>
__global__ void __launch_bounds__(256, 2) gemm_hmma(
    const __nv_bfloat16* __restrict__ A, int lda,
    const __nv_bfloat16* __restrict__ B, int ldb,
    float* __restrict__ out, int ldc, int kPerSplit,
    const float* __restrict__ bias,
    const float* __restrict__ x, __nv_bfloat16* __restrict__ aeb)
{
    extern __shared__ __align__(16) char sm[];
    const int tid  = threadIdx.x;
    const int m0   = blockIdx.y * 128;
    const int n0   = blockIdx.x * 128;
    const int z    = blockIdx.z;
    const int kbase = z * kPerSplit;
    const int S    = kPerSplit / 32;
    const int warp = tid >> 5, lane = tid & 31;
    const int wm   = (warp >> 1) * 32;   // 4 warp-rows of 32
    const int wn   = (warp & 1) * 64;    // 2 warp-cols of 64

    auto prefetch = [&](int s) {
        char* st = sm + (s & 3) * STG_BYTES;
        const int k0 = kbase + s * 32;
        #pragma unroll
        for (int i = 0; i < 2; i++) {
            int c = tid + 256 * i;
            int row = c >> 2, col = (c & 3) * 8;
            const __nv_bfloat16* src = A + (size_t)(m0 + row) * lda + k0 + col;
            CP_ASYNC16(smem_u32(st + row * 80 + col * 2), src);
        }
        #pragma unroll
        for (int i = 0; i < 2; i++) {
            int c = tid + 256 * i;
            int row = c >> 4, col = (c & 15) * 8;
            const __nv_bfloat16* src = B + (size_t)(k0 + row) * ldb + n0 + col;
            CP_ASYNC16(smem_u32(st + 10240 + row * 272 + col * 2), src);
        }
        CP_COMMIT();
    };

    float acc[2][8][4] = {};
    prefetch(0); prefetch(1); prefetch(2);

    for (int s = 0; s < S; s++) {
        int rem = S - 1 - s;
        if (rem >= 2)      asm volatile("cp.async.wait_group 2;\n" ::: "memory");
        else if (rem == 1) asm volatile("cp.async.wait_group 1;\n" ::: "memory");
        else               asm volatile("cp.async.wait_group 0;\n" ::: "memory");
        __syncthreads();
        if (s + 3 < S) prefetch(s + 3);

        const char* st = sm + (s & 3) * STG_BYTES;
        #pragma unroll
        for (int kk = 0; kk < 32; kk += 16) {
            uint32_t af[2][4], bfr[4][4];
            #pragma unroll
            for (int mt = 0; mt < 2; mt++)
                ldmatrix_x4(af[mt], st + (wm + mt * 16 + (lane & 15)) * 80
                                       + (kk + (lane >> 4) * 8) * 2);
            #pragma unroll
            for (int g = 0; g < 4; g++)
                ldmatrix_x4_trans(bfr[g], st + 10240 + (kk + (lane & 15)) * 272
                                              + (wn + g * 16 + (lane >> 4) * 8) * 2);
            #pragma unroll
            for (int mt = 0; mt < 2; mt++)
                #pragma unroll
                for (int nt = 0; nt < 8; nt++)
                    mma_bf16(acc[mt][nt], af[mt],
                             bfr[nt >> 1][(nt & 1) * 2], bfr[nt >> 1][(nt & 1) * 2 + 1]);
        }
    }

    // ---------------- epilogue ----------------
    if (MODE == 0) {
        float* o = out + (size_t)z * (BATCH * ldc);
        #pragma unroll
        for (int mt = 0; mt < 2; mt++) {
            #pragma unroll
            for (int nt = 0; nt < 8; nt++) {
                int r = m0 + wm + mt * 16 + (lane >> 2);
                int c = n0 + wn + nt * 8 + (lane & 3) * 2;
                *reinterpret_cast<float2*>(&o[(size_t)r * ldc + c]) =
                    make_float2(acc[mt][nt][0], acc[mt][nt][1]);
                *reinterpret_cast<float2*>(&o[(size_t)(r + 8) * ldc + c]) =
                    make_float2(acc[mt][nt][2], acc[mt][nt][3]);
            }
        }
    } else {
        #pragma unroll
        for (int mt = 0; mt < 2; mt++) {
            #pragma unroll
            for (int nt = 0; nt < 8; nt++) {
                int c = n0 + wn + nt * 8 + (lane & 3) * 2;
                float b0 = bias[c], b1 = bias[c + 1];
                #pragma unroll
                for (int pr = 0; pr < 2; pr++) {
                    int r = m0 + wm + mt * 16 + (lane >> 2) + 8 * pr;
                    size_t o = (size_t)r * ldc + c;
                    float2 old = *reinterpret_cast<const float2*>(&out[o]);
                    float v0 = acc[mt][nt][2 * pr]     + old.x + b0;
                    float v1 = acc[mt][nt][2 * pr + 1] + old.y + b1;
                    *reinterpret_cast<float2*>(&out[o]) = make_float2(v0, v1);
                    // fused xhat for next step: x - sigmoid(canvas)
                    float xv0 = x[o] - sigmoidf(v0);
                    float xv1 = x[o + 1] - sigmoidf(v1);
                    __nv_bfloat16 h0, l0, h1, l1;
                    split_bf16(xv0, h0, l0);
                    split_bf16(xv1, h1, l1);
                    size_t ab = (size_t)r * KP_ENC + c;
                    aeb[ab]                 = h0; aeb[ab + 1]             = h1;
                    aeb[ab + K_ENC]         = h0; aeb[ab + K_ENC + 1]     = h1;
                    aeb[ab + 2 * K_ENC]     = l0; aeb[ab + 2 * K_ENC + 1] = l1;
                }
            }
        }
    }
}

// ---------------- setup kernels ----------------
__global__ void zero4_kernel(float4* p, int n4) {
    int i = blockIdx.x * blockDim.x + threadIdx.x;
    if (i < n4) p[i] = make_float4(0.f, 0.f, 0.f, 0.f);
}

// Fold patch extraction + stack [pixels | enc_rec | 2x h_dec]; split hi/lo rows [Whi; Wlo; Whi]
__global__ void build_w1_kernel(const float* __restrict__ ek, const float* __restrict__ er) {
    int idx = blockIdx.x * blockDim.x + threadIdx.x;
    if (idx >= K_ENC * GATE) return;
    int row = idx / GATE;
    int n   = idx - row * GATE;
    float v;
    if (row < PIX) {
        int r = row >> 6, c = row & 63;
        v = 0.f;
        #pragma unroll
        for (int dr = 0; dr < 3; dr++) {
            int rr = r - dr;
            if (rr >= 0 && (rr & 1) == 0) {
                int pr = rr >> 1;
                #pragma unroll
                for (int dc = 0; dc < 3; dc++) {
                    int cc = c - dc;
                    if (cc >= 0 && (cc & 1) == 0) {
                        int pc = cc >> 1;
                        v += ek[(((pr * 32 + pc) * 9) + dr * 3 + dc) * GATE + n];
                    }
                }
            }
        }
    } else if (row < PIX + UNITS) {
        v = er[(row - PIX) * GATE + n];
    } else {
        int u = row - PIX - UNITS;
        v = ek[(9216 + u) * GATE + n] + ek[(9472 + u) * GATE + n];
    }
    __nv_bfloat16 hi, lo; split_bf16(v, hi, lo);
    g_Be[(size_t)row * GATE + n]               = hi;
    g_Be[(size_t)(K_ENC + row) * GATE + n]     = lo;
    g_Be[(size_t)(2 * K_ENC + row) * GATE + n] = hi;
}

__global__ void build_w2_kernel(const float* __restrict__ dk, const float* __restrict__ dr) {
    int idx = blockIdx.x * blockDim.x + threadIdx.x;
    if (idx >= K_DEC * GATE) return;
    int row = idx / GATE;
    int n   = idx - row * GATE;
    float v = (row < UNITS) ? dk[row * GATE + n] : dr[(row - UNITS) * GATE + n];
    __nv_bfloat16 hi, lo; split_bf16(v, hi, lo);
    g_Bd[row * GATE + n]               = hi;
    g_Bd[(K_DEC + row) * GATE + n]     = lo;
    g_Bd[(2 * K_DEC + row) * GATE + n] = hi;
}

__global__ void build_wc_kernel(const float* __restrict__ wd) {
    int idx = blockIdx.x * blockDim.x + threadIdx.x;
    if (idx >= K_CAN * PIX) return;
    int row = idx / PIX;
    int n   = idx - row * PIX;
    float v = wd[idx];
    __nv_bfloat16 hi, lo; split_bf16(v, hi, lo);
    g_Bc[row * PIX + n]               = hi;
    g_Bc[(K_CAN + row) * PIX + n]     = lo;
    g_Bc[(2 * K_CAN + row) * PIX + n] = hi;
}

// initial xhat (canvas = 0)
__global__ void xhat0_kernel(const float* __restrict__ x) {
    int i = blockIdx.x * blockDim.x + threadIdx.x;   // BATCH*PIX
    int b = i >> 12, p = i & (PIX - 1);
    float v = x[i] - 0.5f;
    __nv_bfloat16 hi, lo; split_bf16(v, hi, lo);
    size_t base = (size_t)b * KP_ENC + p;
    g_Aeb[base]             = hi;
    g_Aeb[base + K_ENC]     = hi;
    g_Aeb[base + 2 * K_ENC] = lo;
}

// ---------------- fused enc LSTM (9-way split reduce) + attention ----------------
__global__ void lstm_enc_attn_kernel(const float* __restrict__ part,
                                     const float* __restrict__ bias,
                                     const float* __restrict__ Wenc,
                                     const float* __restrict__ benc) {
    const int b = blockIdx.x;     // 512 blocks
    const int u = threadIdx.x;    // 256 threads
    __shared__ float sh[UNITS];
    __shared__ float lg[10];
    __shared__ float attn[10];

    float gi = bias[u], gf = bias[UNITS + u], gg = bias[2 * UNITS + u], go = bias[3 * UNITS + u];
    const size_t roff = (size_t)b * GATE + u;
    #pragma unroll
    for (int s = 0; s < ENC_SPLITS; s++) {
        const float* p = part + (size_t)s * (BATCH * GATE) + roff;
        gi += p[0]; gf += p[UNITS]; gg += p[2 * UNITS]; go += p[3 * UNITS];
    }
    int idx = b * UNITS + u;
    float cn = sigmoidf(gf) * g_ce[idx] + sigmoidf(gi) * tanhf(gg);
    float hn = sigmoidf(go) * tanhf(cn);
    g_ce[idx] = cn;
    sh[u] = hn;
    {
        __nv_bfloat16 hi, lo; split_bf16(hn, hi, lo);
        size_t base = (size_t)b * KP_ENC + PIX + u;
        g_Aeb[base]             = hi;
        g_Aeb[base + K_ENC]     = hi;
        g_Aeb[base + 2 * K_ENC] = lo;
    }
    if (u < 10) lg[u] = benc[u];
    __syncthreads();

    // attention logits + softmax + z = attn @ Wenc^T
    float p10[10];
    float hv = sh[u];
    #pragma unroll
    for (int j = 0; j < 10; j++) p10[j] = hv * Wenc[u * 10 + j];
    #pragma unroll
    for (int j = 0; j < 10; j++)
        #pragma unroll
        for (int off = 16; off > 0; off >>= 1)
            p10[j] += __shfl_down_sync(0xffffffffu, p10[j], off);
    if ((u & 31) == 0)
        for (int j = 0; j < 10; j++) atomicAdd(&lg[j], p10[j]);
    __syncthreads();
    if (u == 0) {
        float m = lg[0];
        for (int j = 1; j < 10; j++) m = fmaxf(m, lg[j]);
        float ssum = 0.f, e[10];
        for (int j = 0; j < 10; j++) { e[j] = expf(lg[j] - m); ssum += e[j]; }
        float inv = 1.f / ssum;
        for (int j = 0; j < 10; j++) attn[j] = e[j] * inv;
    }
    __syncthreads();
    float zacc = 0.f;
    #pragma unroll
    for (int j = 0; j < 10; j++) zacc += attn[j] * Wenc[u * 10 + j];
    __nv_bfloat16 hi, lo; split_bf16(zacc, hi, lo);
    size_t bd = (size_t)b * KP_DEC + u;
    g_Adb[bd]             = hi;
    g_Adb[bd + K_DEC]     = hi;
    g_Adb[bd + 2 * K_DEC] = lo;
}

// ---------------- dec LSTM (4-way split reduce) ----------------
__global__ void lstm_dec_kernel(const float* __restrict__ part, const float* __restrict__ bias) {
    int idx = blockIdx.x * blockDim.x + threadIdx.x;  // BATCH*UNITS
    int b = idx / UNITS, u = idx - b * UNITS;
    float gi = bias[u], gf = bias[UNITS + u], gg = bias[2 * UNITS + u], go = bias[3 * UNITS + u];
    size_t roff = (size_t)b * GATE + u;
    #pragma unroll
    for (int s = 0; s < DEC_SPLITS; s++) {
        const float* p = part + (size_t)s * (BATCH * GATE) + roff;
        gi += p[0]; gf += p[UNITS]; gg += p[2 * UNITS]; go += p[3 * UNITS];
    }
    float cn = sigmoidf(gf) * g_cd[idx] + sigmoidf(gi) * tanhf(gg);
    float hn = sigmoidf(go) * tanhf(cn);
    g_cd[idx] = cn;
    __nv_bfloat16 hi, lo; split_bf16(hn, hi, lo);
    size_t be = (size_t)b * KP_ENC + PIX + UNITS + u;
    g_Aeb[be]             = hi;
    g_Aeb[be + K_ENC]     = hi;
    g_Aeb[be + 2 * K_ENC] = lo;
    size_t bd = (size_t)b * KP_DEC + UNITS + u;
    g_Adb[bd]             = hi;
    g_Adb[bd + K_DEC]     = hi;
    g_Adb[bd + 2 * K_DEC] = lo;
    size_t bc = (size_t)b * KP_CAN + u;
    g_Acb[bc]             = hi;
    g_Acb[bc + K_CAN]     = hi;
    g_Acb[bc + 2 * K_CAN] = lo;
}

// ---------------- launcher ----------------
extern "C" void kernel_launch(void* const* d_in, const int* in_sizes, int n_in,
                              void* d_out, int out_size) {
    const float* x          = (const float*)d_in[0];
    const float* enc_kernel = (const float*)d_in[1];
    const float* enc_rec    = (const float*)d_in[2];
    const float* enc_bias   = (const float*)d_in[3];
    const float* dec_kernel = (const float*)d_in[4];
    const float* dec_rec    = (const float*)d_in[5];
    const float* dec_bias   = (const float*)d_in[6];
    const float* W_enc      = (const float*)d_in[7];
    const float* b_enc      = (const float*)d_in[8];
    const float* W_dec      = (const float*)d_in[9];
    const float* b_dec      = (const float*)d_in[10];
    float* canvas = (float*)d_out;

    __nv_bfloat16 *Ae, *Ad, *Ac, *Be, *Bd, *Bc;
    float *part, *ce, *cd;
    cudaGetSymbolAddress((void**)&Ae,  g_Aeb);
    cudaGetSymbolAddress((void**)&Ad,  g_Adb);
    cudaGetSymbolAddress((void**)&Ac,  g_Acb);
    cudaGetSymbolAddress((void**)&Be,  g_Be);
    cudaGetSymbolAddress((void**)&Bd,  g_Bd);
    cudaGetSymbolAddress((void**)&Bc,  g_Bc);
    cudaGetSymbolAddress((void**)&part, g_part);
    cudaGetSymbolAddress((void**)&ce,  g_ce);
    cudaGetSymbolAddress((void**)&cd,  g_cd);

    cudaFuncSetAttribute(gemm_hmma<0>, cudaFuncAttributeMaxDynamicSharedMemorySize, GEMM_SMEM);
    cudaFuncSetAttribute(gemm_hmma<1>, cudaFuncAttributeMaxDynamicSharedMemorySize, GEMM_SMEM);

    // ---- setup: pack weights (bf16 hi/lo), zero states, initial xhat ----
    build_w1_kernel<<<(K_ENC * GATE + 255) / 256, 256>>>(enc_kernel, enc_rec);
    build_w2_kernel<<<(K_DEC * GATE + 255) / 256, 256>>>(dec_kernel, dec_rec);
    build_wc_kernel<<<(K_CAN * PIX + 255) / 256, 256>>>(W_dec);
    zero4_kernel<<<(BATCH * PIX / 4 + 255) / 256, 256>>>((float4*)canvas, BATCH * PIX / 4);
    zero4_kernel<<<(BATCH * KP_ENC / 8 + 255) / 256, 256>>>((float4*)Ae, BATCH * KP_ENC / 8);
    zero4_kernel<<<(BATCH * KP_DEC / 8 + 255) / 256, 256>>>((float4*)Ad, BATCH * KP_DEC / 8);
    zero4_kernel<<<(BATCH * KP_CAN / 8 + 255) / 256, 256>>>((float4*)Ac, BATCH * KP_CAN / 8);
    zero4_kernel<<<(BATCH * UNITS / 4 + 255) / 256, 256>>>((float4*)ce, BATCH * UNITS / 4);
    zero4_kernel<<<(BATCH * UNITS / 4 + 255) / 256, 256>>>((float4*)cd, BATCH * UNITS / 4);
    xhat0_kernel<<<(BATCH * PIX) / 256, 256>>>(x);

    // ---- 10 sequential DRAW steps (5 launches/step) ----
    for (int t = 0; t < STEPS; t++) {
        // enc gates (split-K partials)
        gemm_hmma<0><<<dim3(GATE / 128, BATCH / 128, ENC_SPLITS), 256, GEMM_SMEM>>>(
            Ae, KP_ENC, Be, GATE, part, GATE, KP_ENC / ENC_SPLITS, nullptr, nullptr, nullptr);

        // enc LSTM + attention (fused)
        lstm_enc_attn_kernel<<<BATCH, 256>>>(part, enc_bias, W_enc, b_enc);

        // dec gates (split-K partials)
        gemm_hmma<0><<<dim3(GATE / 128, BATCH / 128, DEC_SPLITS), 256, GEMM_SMEM>>>(
            Ad, KP_DEC, Bd, GATE, part, GATE, KP_DEC / DEC_SPLITS, nullptr, nullptr, nullptr);

        // dec LSTM
        lstm_dec_kernel<<<(BATCH * UNITS) / 256, 256>>>(part, dec_bias);

        // canvas += h_dec @ W_dec + b_dec, fused next-step xhat
        gemm_hmma<1><<<dim3(PIX / 128, BATCH / 128, 1), 256, GEMM_SMEM>>>(
            Ac, KP_CAN, Bc, PIX, canvas, PIX, KP_CAN, b_dec, x, Ae);
    }
}